// round 12
// baseline (speedup 1.0000x reference)
#include <cuda_runtime.h>
#include <cuda_fp16.h>

#define BB 4
#define HHH 64
#define LL 4096
#define EE 192
#define NNS 16
#define RR 6
#define KK 4
#define DM 96
#define BL (BB*LL)
#define C152 152
#define NCH 32
#define CHL 128   // LL/NCH

typedef unsigned long long u64;

// ------------------------- device scratch (no allocations) ------------------
__device__ float g_xx[BL*EE];
__device__ float g_z [BL*EE];
__device__ float g_xc[BL*EE];
__device__ float g_P [BL*C152];
__device__ __half2 g_dU[16*EE*LL];     // {delta, delta*u} per (bk,e,l)
__device__ float g_B4[16*LL*16];
__device__ float g_C4[16*LL*16];
__device__ float g_y [16*LL*EE];       // (bk, l, e)
__device__ float g_ym[BL*EE];
// chunked-scan carries: chain = bk*EE+e in [0,3072); state slot np = lj*4+s
__device__ float g_hfin[3072*NCH*16];
__device__ float g_hin [3072*NCH*16];
__device__ float g_Sdd [3072*NCH];

__device__ __forceinline__ float ex2f(float x){
    float y; asm("ex2.approx.f32 %0, %1;" : "=f"(y) : "f"(x)); return y;
}
__device__ __forceinline__ float siluf(float x){
    return x / (1.f + __expf(-x));
}
__device__ __forceinline__ float softplusf(float x){
    return fmaxf(x, 0.f) + __logf(1.f + __expf(-fabsf(x)));
}
__device__ __forceinline__ u64 fma2(u64 a, u64 b, u64 c){
    u64 d; asm("fma.rn.f32x2 %0, %1, %2, %3;" : "=l"(d) : "l"(a), "l"(b), "l"(c));
    return d;
}
__device__ __forceinline__ u64 pack2(float x, float y){
    u64 d; asm("mov.b64 %0, {%1, %2};" : "=l"(d) : "f"(x), "f"(y));
    return d;
}
__device__ __forceinline__ void unpack2(u64 v, float& lo, float& hi){
    asm("mov.b64 {%0, %1}, %2;" : "=f"(lo), "=f"(hi) : "l"(v));
}

// ------------------------- tiled GEMM: out[m,n] = sum_k X[m,k]*W[n,k] -------
// 128x64 tile, 256 threads, 8x4 micro-tile, f32x2 packed accumulation,
// register-prefetch software pipeline over k-tiles.
template<int KD, int MODE>
__global__ void __launch_bounds__(256)
k_gemm(const float* __restrict__ Xp, const float* __restrict__ W,
       float* __restrict__ Out, int Nn)
{
    __shared__ float Xs[32][132];
    __shared__ float Ws[32][68];
    const float* __restrict__ X = (MODE==0) ? (const float*)g_xc
                                : (MODE==2) ? (const float*)g_ym : Xp;
    const int m0 = blockIdx.x * 128;
    const int n0 = blockIdx.y * 64;
    const int t  = threadIdx.x;
    const int ty = t >> 4, tx = t & 15;
    u64 acc2[4][4];
    #pragma unroll
    for (int i=0;i<4;i++)
        #pragma unroll
        for (int j=0;j<4;j++) acc2[i][j] = 0ull;

    const int lc4 = (t & 7) * 4;
    const int lr0 = t >> 3;
    const int NKC = KD/32;

    float4 xv[4], wv2[2];
    #pragma unroll
    for (int i = 0; i < 4; i++)
        xv[i] = *(const float4*)&X[(m0 + lr0 + 32*i)*KD + lc4];
    #pragma unroll
    for (int i = 0; i < 2; i++){
        int nr = n0 + lr0 + 32*i;
        wv2[i] = (nr < Nn) ? *(const float4*)&W[nr*KD + lc4]
                           : make_float4(0.f,0.f,0.f,0.f);
    }

    #pragma unroll
    for (int kc = 0; kc < NKC; kc++){
        #pragma unroll
        for (int i = 0; i < 4; i++){
            int r = lr0 + 32*i;
            Xs[lc4+0][r] = xv[i].x; Xs[lc4+1][r] = xv[i].y;
            Xs[lc4+2][r] = xv[i].z; Xs[lc4+3][r] = xv[i].w;
        }
        #pragma unroll
        for (int i = 0; i < 2; i++){
            int r = lr0 + 32*i;
            Ws[lc4+0][r] = wv2[i].x; Ws[lc4+1][r] = wv2[i].y;
            Ws[lc4+2][r] = wv2[i].z; Ws[lc4+3][r] = wv2[i].w;
        }
        __syncthreads();

        if (kc + 1 < NKC){
            #pragma unroll
            for (int i = 0; i < 4; i++)
                xv[i] = *(const float4*)&X[(m0 + lr0 + 32*i)*KD + (kc+1)*32 + lc4];
            #pragma unroll
            for (int i = 0; i < 2; i++){
                int nr = n0 + lr0 + 32*i;
                wv2[i] = (nr < Nn) ? *(const float4*)&W[nr*KD + (kc+1)*32 + lc4]
                                   : make_float4(0.f,0.f,0.f,0.f);
            }
        }

        #pragma unroll
        for (int k = 0; k < 32; k++){
            const u64* xp = (const u64*)&Xs[k][ty*8];
            u64 x2[4] = {xp[0], xp[1], xp[2], xp[3]};
            float4 wv = *(const float4*)&Ws[k][tx*4];
            u64 w2[4] = {pack2(wv.x,wv.x), pack2(wv.y,wv.y),
                         pack2(wv.z,wv.z), pack2(wv.w,wv.w)};
            #pragma unroll
            for (int i=0;i<4;i++)
                #pragma unroll
                for (int j=0;j<4;j++) acc2[i][j] = fma2(x2[i], w2[j], acc2[i][j]);
        }
        __syncthreads();
    }
    #pragma unroll
    for (int i=0;i<4;i++){
        #pragma unroll
        for (int j=0;j<4;j++){
            float lo, hi;
            unpack2(acc2[i][j], lo, hi);
            int n = n0 + tx*4 + j;
            int mA = m0 + ty*8 + 2*i;
            #pragma unroll
            for (int pp = 0; pp < 2; pp++){
                int m = mA + pp;
                float v = pp ? hi : lo;
                if (MODE == 1){
                    if (n < EE) g_xx[m*EE + n] = v;
                    else        g_z [m*EE + n - EE] = siluf(v);
                } else if (MODE == 0){
                    if (n < Nn) g_P[m*C152 + n] = v;
                } else {
                    if (n < Nn) Out[m*Nn + n] = v;
                }
            }
        }
    }
}

// ------------------------- depthwise 3x3 conv + bias + silu -----------------
__global__ void __launch_bounds__(256) k_conv(const float* __restrict__ cw, const float* __restrict__ cb)
{
    __shared__ float xs_s[3][64][48];
    __shared__ float cw_s[48][9];
    const int e0 = blockIdx.x * 48;
    const int h  = blockIdx.y;
    const int b  = blockIdx.z;
    const int t  = threadIdx.x;

    for (int idx = t; idx < 3*64*48; idx += 256){
        int row = idx / (64*48);
        int rem = idx - row*(64*48);
        int w  = rem / 48;
        int ec = rem - w*48;
        int hh = h + row - 1;
        float v = 0.f;
        if (hh >= 0 && hh < HHH)
            v = g_xx[(b*LL + hh*64 + w)*EE + e0 + ec];
        xs_s[row][w][ec] = v;
    }
    for (int idx = t; idx < 48*9; idx += 256){
        int ec = idx / 9, q = idx - ec*9;
        cw_s[ec][q] = cw[(e0+ec)*9 + q];
    }
    __syncthreads();

    for (int o = t; o < 64*48; o += 256){
        int w  = o / 48;
        int ec = o - w*48;
        float acc = cb[e0+ec];
        #pragma unroll
        for (int dh = 0; dh < 3; dh++){
            #pragma unroll
            for (int dw = 0; dw < 3; dw++){
                int ww = w + dw - 1;
                if (ww >= 0 && ww < 64)
                    acc = fmaf(xs_s[dh][ww][ec], cw_s[ec][dh*3+dw], acc);
            }
        }
        g_xc[(b*LL + h*64 + w)*EE + e0 + ec] = siluf(acc);
    }
}

// ------------------------- prep: {delta, du} half2 + B4/C4 ------------------
// B4/C4 slot layout per l: np = lj*4 + s  <->  state n = 4*s + lj
__global__ void __launch_bounds__(256) k_prep(const float* __restrict__ dtw, const float* __restrict__ dtb)
{
    __shared__ float Pt[32][39];
    __shared__ float xr[32][193];
    __shared__ float dtws[EE*RR];
    __shared__ float dtbs[EE];
    __shared__ int   clm[32];
    const int bid = blockIdx.x;
    const int lt = bid & 127;
    const int k  = (bid >> 7) & 3;
    const int b  = bid >> 9;
    const int l0 = lt * 32;
    const int t  = threadIdx.x;

    if (t < 32){
        int l = l0 + t, cl;
        if (k == 0)      cl = l;
        else if (k == 1) cl = (l & 63)*64 + (l >> 6);
        else if (k == 2) cl = (LL-1) - l;
        else { int lp = (LL-1) - l; cl = (lp & 63)*64 + (lp >> 6); }
        clm[t] = cl;
    }
    for (int idx = t; idx < EE*RR; idx += 256) dtws[idx] = dtw[k*EE*RR + idx];
    for (int idx = t; idx < EE;    idx += 256) dtbs[idx] = dtb[k*EE + idx];
    __syncthreads();
    for (int idx = t; idx < 32*38; idx += 256){
        int r = idx / 38, c = idx - r*38;
        Pt[r][c] = g_P[(b*LL + clm[r])*C152 + k*38 + c];
    }
    for (int idx = t; idx < 32*48; idx += 256){
        int r = idx / 48, c = idx - r*48;
        float4 v = *(const float4*)&g_xc[(b*LL + clm[r])*EE + c*4];
        xr[r][c*4+0] = v.x; xr[r][c*4+1] = v.y;
        xr[r][c*4+2] = v.z; xr[r][c*4+3] = v.w;
    }
    __syncthreads();

    const int warp = t >> 5, lane = t & 31;
    const int bk = b*KK + k;
    for (int e = warp; e < EE; e += 8){
        float acc = dtbs[e];
        #pragma unroll
        for (int r = 0; r < RR; r++) acc = fmaf(Pt[lane][r], dtws[e*RR + r], acc);
        float dl = softplusf(acc);
        float u  = xr[lane][e];
        g_dU[(bk*EE + e)*LL + l0 + lane] = __floats2half2_rn(dl, dl*u);
    }
    for (int idx = t; idx < 32*16; idx += 256){
        int pos = idx >> 4, np = idx & 15;
        int n = 4*(np & 3) + (np >> 2);     // state index for slot np
        int o = (bk*LL + l0 + pos)*16 + np;
        g_B4[o] = Pt[pos][6  + n];
        g_C4[o] = Pt[pos][22 + n];
    }
}

// ------------------------- scan pass 1: per-chunk local (h_fin, Sdd) --------
// block = (bk, chunk, e-group-triplet): 8 warps share (bk, chunk), stage B
// into smem once; warp w covers e-group (egb*8+w). chunks 0..30 only.
// grid 16*31*3 = 1488 blocks x 256.
__global__ void __launch_bounds__(256) k_scan1(const float* __restrict__ A_logs)
{
    __shared__ float Bs[CHL*16];       // 8KB

    const int warp = threadIdx.x >> 5;
    const int lane = threadIdx.x & 31;
    int tmp = blockIdx.x;
    const int egb   = tmp % 3;  tmp /= 3;
    const int chunk = tmp % 31; tmp /= 31;
    const int bk    = tmp;
    const int eg = egb*8 + warp;                 // [0,24)
    const int e  = eg*8 + (lane >> 2);
    const int lj = lane & 3;
    const int k  = bk & 3;
    const int t  = threadIdx.x;
    const int l0 = chunk*CHL;

    // stage B tile (contiguous 8KB)
    {
        const float4* src = (const float4*)(g_B4 + ((long)bk*LL + l0)*16);
        float4* dst = (float4*)Bs;
        #pragma unroll
        for (int i = 0; i < 2; i++) dst[t + 256*i] = src[t + 256*i];
    }

    const float L2E = 1.4426950408889634f;
    float am[4]; bool okl = true;
    #pragma unroll
    for (int s = 0; s < 4; s++){
        int n = 4*s + lj;
        float av = -__expf(A_logs[(k*EE + e)*NNS + n]);
        am[s] = av * L2E;
        okl &= fabsf(av + (float)(n+1)) < 1e-4f * (float)(n+1);
    }
    const bool ok = __all_sync(0xffffffffu, okl);

    const int ch = bk*EE + e;
    const __half2* __restrict__ pdu = g_dU + (long)ch*LL + l0;

    __syncthreads();

    float h0=0.f, h1=0.f, h2=0.f, h3=0.f, sdd = 0.f;
    const float am0 = am[0];

    if (ok){
        for (int l = 0; l < CHL; l += 4){
            uint4 q = *(const uint4*)(pdu + l);
            float2 f0 = __half22float2(*reinterpret_cast<const __half2*>(&q.x));
            float2 f1 = __half22float2(*reinterpret_cast<const __half2*>(&q.y));
            float2 f2 = __half22float2(*reinterpret_cast<const __half2*>(&q.z));
            float2 f3 = __half22float2(*reinterpret_cast<const __half2*>(&q.w));
            float dd[4] = {f0.x, f1.x, f2.x, f3.x};
            float uu[4] = {f0.y, f1.y, f2.y, f3.y};
            #pragma unroll
            for (int s = 0; s < 4; s++){
                float4 b4 = *(const float4*)(Bs + (l+s)*16 + lj*4);
                float tt = ex2f(dd[s]*am0);
                float q4 = __shfl_sync(0xffffffffu, tt, 3, 4);
                float dA1 = tt*q4, dA2 = dA1*q4, dA3 = dA2*q4;
                float us = uu[s];
                h0 = fmaf(tt,  h0, us*b4.x);
                h1 = fmaf(dA1, h1, us*b4.y);
                h2 = fmaf(dA2, h2, us*b4.z);
                h3 = fmaf(dA3, h3, us*b4.w);
            }
            sdd += dd[0] + dd[1] + dd[2] + dd[3];
        }
    } else {
        #pragma unroll 1
        for (int l = 0; l < CHL; l += 4){
            uint4 q = *(const uint4*)(pdu + l);
            float2 f0 = __half22float2(*reinterpret_cast<const __half2*>(&q.x));
            float2 f1 = __half22float2(*reinterpret_cast<const __half2*>(&q.y));
            float2 f2 = __half22float2(*reinterpret_cast<const __half2*>(&q.z));
            float2 f3 = __half22float2(*reinterpret_cast<const __half2*>(&q.w));
            float dd[4] = {f0.x, f1.x, f2.x, f3.x};
            float uu[4] = {f0.y, f1.y, f2.y, f3.y};
            #pragma unroll
            for (int s = 0; s < 4; s++){
                float4 b4 = *(const float4*)(Bs + (l+s)*16 + lj*4);
                float us = uu[s];
                h0 = fmaf(ex2f(dd[s]*am[0]), h0, us*b4.x);
                h1 = fmaf(ex2f(dd[s]*am[1]), h1, us*b4.y);
                h2 = fmaf(ex2f(dd[s]*am[2]), h2, us*b4.z);
                h3 = fmaf(ex2f(dd[s]*am[3]), h3, us*b4.w);
            }
            sdd += dd[0] + dd[1] + dd[2] + dd[3];
        }
    }
    int hb = (ch*NCH + chunk)*16 + lj*4;
    *(float4*)&g_hfin[hb] = make_float4(h0, h1, h2, h3);
    if (lj == 0) g_Sdd[ch*NCH + chunk] = sdd;
}

// ------------------------- scan mid: carry propagation ----------------------
// thread = (chain, np). grid 192 x 256.
__global__ void __launch_bounds__(256) k_scanmid(const float* __restrict__ A_logs)
{
    const int tid = blockIdx.x*256 + threadIdx.x;   // [0, 49152)
    const int ch = tid >> 4;
    const int np = tid & 15;
    const int n  = 4*(np & 3) + (np >> 2);
    const int e  = ch % EE;
    const int k  = (ch / EE) & 3;
    float a = -__expf(A_logs[(k*EE + e)*NNS + n]);

    float h = 0.f;
    #pragma unroll
    for (int c = 0; c < NCH; c++){
        g_hin[(ch*NCH + c)*16 + np] = h;
        if (c < NCH-1){
            float hf = g_hfin[(ch*NCH + c)*16 + np];
            float S = g_Sdd[ch*NCH + c];
            h = hf + __expf(a*S)*h;
        }
    }
}

// ------------------------- scan pass 2: full scan, y in (bk,l,e) ------------
// block = (bk, chunk, e-group-triplet): stage B and C into smem.
// all 32 chunks. grid 16*32*3 = 1536 blocks x 256.
__global__ void __launch_bounds__(256) k_scan2(const float* __restrict__ A_logs)
{
    __shared__ float Bs[CHL*16];       // 8KB
    __shared__ float Cs[CHL*16];       // 8KB

    const int warp = threadIdx.x >> 5;
    const int lane = threadIdx.x & 31;
    int tmp = blockIdx.x;
    const int egb   = tmp % 3;  tmp /= 3;
    const int chunk = tmp & 31;
    const int bk    = tmp >> 5;
    const int eg = egb*8 + warp;
    const int e  = eg*8 + (lane >> 2);
    const int lj = lane & 3;
    const int k  = bk & 3;
    const int t  = threadIdx.x;
    const int l0 = chunk*CHL;

    // stage B and C tiles (contiguous 8KB each)
    {
        const float4* srcB = (const float4*)(g_B4 + ((long)bk*LL + l0)*16);
        const float4* srcC = (const float4*)(g_C4 + ((long)bk*LL + l0)*16);
        float4* dstB = (float4*)Bs;
        float4* dstC = (float4*)Cs;
        #pragma unroll
        for (int i = 0; i < 2; i++){
            dstB[t + 256*i] = srcB[t + 256*i];
            dstC[t + 256*i] = srcC[t + 256*i];
        }
    }

    const float L2E = 1.4426950408889634f;
    float am[4]; bool okl = true;
    #pragma unroll
    for (int s = 0; s < 4; s++){
        int n = 4*s + lj;
        float av = -__expf(A_logs[(k*EE + e)*NNS + n]);
        am[s] = av * L2E;
        okl &= fabsf(av + (float)(n+1)) < 1e-4f * (float)(n+1);
    }
    const bool ok = __all_sync(0xffffffffu, okl);

    const int ch = bk*EE + e;
    const __half2* __restrict__ pdu = g_dU + (long)ch*LL + l0;
    float* __restrict__ py = g_y + ((long)bk*LL + l0)*EE;

    float4 h4 = *(const float4*)&g_hin[(ch*NCH + chunk)*16 + lj*4];
    float h0 = h4.x, h1 = h4.y, h2 = h4.z, h3 = h4.w;
    const float am0 = am[0];

    __syncthreads();

    if (ok){
        for (int l = 0; l < CHL; l += 4){
            uint4 q = *(const uint4*)(pdu + l);
            float2 f0 = __half22float2(*reinterpret_cast<const __half2*>(&q.x));
            float2 f1 = __half22float2(*reinterpret_cast<const __half2*>(&q.y));
            float2 f2 = __half22float2(*reinterpret_cast<const __half2*>(&q.z));
            float2 f3 = __half22float2(*reinterpret_cast<const __half2*>(&q.w));
            float dd[4] = {f0.x, f1.x, f2.x, f3.x};
            float uu[4] = {f0.y, f1.y, f2.y, f3.y};
            float ysv = 0.f;
            #pragma unroll
            for (int s = 0; s < 4; s++){
                float4 b4 = *(const float4*)(Bs + (l+s)*16 + lj*4);
                float4 c4 = *(const float4*)(Cs + (l+s)*16 + lj*4);
                float tt = ex2f(dd[s]*am0);
                float q4 = __shfl_sync(0xffffffffu, tt, 3, 4);
                float dA1 = tt*q4, dA2 = dA1*q4, dA3 = dA2*q4;
                float us = uu[s];
                h0 = fmaf(tt,  h0, us*b4.x);
                h1 = fmaf(dA1, h1, us*b4.y);
                h2 = fmaf(dA2, h2, us*b4.z);
                h3 = fmaf(dA3, h3, us*b4.w);
                float p = h0*c4.x;
                p = fmaf(h1, c4.y, p);
                p = fmaf(h2, c4.z, p);
                p = fmaf(h3, c4.w, p);
                p += __shfl_xor_sync(0xffffffffu, p, 1);
                p += __shfl_xor_sync(0xffffffffu, p, 2);
                if (lj == s) ysv = p;
            }
            py[(long)(l + lj)*EE + e] = ysv;
        }
    } else {
        #pragma unroll 1
        for (int l = 0; l < CHL; l += 4){
            uint4 q = *(const uint4*)(pdu + l);
            float2 f0 = __half22float2(*reinterpret_cast<const __half2*>(&q.x));
            float2 f1 = __half22float2(*reinterpret_cast<const __half2*>(&q.y));
            float2 f2 = __half22float2(*reinterpret_cast<const __half2*>(&q.z));
            float2 f3 = __half22float2(*reinterpret_cast<const __half2*>(&q.w));
            float dd[4] = {f0.x, f1.x, f2.x, f3.x};
            float uu[4] = {f0.y, f1.y, f2.y, f3.y};
            float ysv = 0.f;
            #pragma unroll
            for (int s = 0; s < 4; s++){
                float4 b4 = *(const float4*)(Bs + (l+s)*16 + lj*4);
                float4 c4 = *(const float4*)(Cs + (l+s)*16 + lj*4);
                float us = uu[s];
                h0 = fmaf(ex2f(dd[s]*am[0]), h0, us*b4.x);
                h1 = fmaf(ex2f(dd[s]*am[1]), h1, us*b4.y);
                h2 = fmaf(ex2f(dd[s]*am[2]), h2, us*b4.z);
                h3 = fmaf(ex2f(dd[s]*am[3]), h3, us*b4.w);
                float p = h0*c4.x;
                p = fmaf(h1, c4.y, p);
                p = fmaf(h2, c4.z, p);
                p = fmaf(h3, c4.w, p);
                p += __shfl_xor_sync(0xffffffffu, p, 1);
                p += __shfl_xor_sync(0xffffffffu, p, 2);
                if (lj == s) ysv = p;
            }
            py[(long)(l + lj)*EE + e] = ysv;
        }
    }
}

// ------------------------- merge + D*xc + LayerNorm + gate ------------------
// block = 32 l x 8 threads; all reads are contiguous 192-float rows
__global__ void __launch_bounds__(256) k_merge(const float* __restrict__ Ds, const float* __restrict__ gamma,
                        const float* __restrict__ beta)
{
    __shared__ float sumD[EE];
    const int l0 = blockIdx.x * 32;
    const int b  = blockIdx.y;
    const int t  = threadIdx.x;
    if (t < EE) sumD[t] = Ds[t] + Ds[EE + t] + Ds[2*EE + t] + Ds[3*EE + t];
    __syncthreads();

    const int li = t >> 3, ts = t & 7;
    const int l  = l0 + li;
    const int lw = (l & 63)*64 + (l >> 6);

    const float* __restrict__ y0p = g_y + ((long)(b*4 + 0)*LL + l)*EE;
    const float* __restrict__ y1p = g_y + ((long)(b*4 + 1)*LL + lw)*EE;
    const float* __restrict__ y2p = g_y + ((long)(b*4 + 2)*LL + (LL-1-l))*EE;
    const float* __restrict__ y3p = g_y + ((long)(b*4 + 3)*LL + (LL-1-lw))*EE;
    const float* __restrict__ xcp = g_xc + (long)(b*LL + l)*EE;
    const float* __restrict__ zp  = g_z  + (long)(b*LL + l)*EE;
    float* __restrict__ ymp = g_ym + (long)(b*LL + l)*EE;

    float v[6][4];
    float s1 = 0.f, s2 = 0.f;
    #pragma unroll
    for (int m = 0; m < 6; m++){
        int e4 = (ts + 8*m)*4;
        float4 a0 = *(const float4*)(y0p + e4);
        float4 a1 = *(const float4*)(y1p + e4);
        float4 a2 = *(const float4*)(y2p + e4);
        float4 a3 = *(const float4*)(y3p + e4);
        float4 xc = *(const float4*)(xcp + e4);
        float4 sd = *(const float4*)(&sumD[e4]);
        v[m][0] = a0.x + a1.x + a2.x + a3.x + sd.x*xc.x;
        v[m][1] = a0.y + a1.y + a2.y + a3.y + sd.y*xc.y;
        v[m][2] = a0.z + a1.z + a2.z + a3.z + sd.z*xc.z;
        v[m][3] = a0.w + a1.w + a2.w + a3.w + sd.w*xc.w;
        #pragma unroll
        for (int q = 0; q < 4; q++){ s1 += v[m][q]; s2 += v[m][q]*v[m][q]; }
    }
    #pragma unroll
    for (int o = 1; o < 8; o <<= 1){
        s1 += __shfl_xor_sync(0xffffffffu, s1, o);
        s2 += __shfl_xor_sync(0xffffffffu, s2, o);
    }
    const float inv = 1.f / (float)EE;
    float mu = s1 * inv;
    float var = s2 * inv - mu*mu;
    float rstd = rsqrtf(var + 1e-5f);

    #pragma unroll
    for (int m = 0; m < 6; m++){
        int e4 = (ts + 8*m)*4;
        float4 gm = *(const float4*)(gamma + e4);
        float4 bt = *(const float4*)(beta + e4);
        float4 zz = *(const float4*)(zp + e4);
        float4 o4;
        o4.x = ((v[m][0]-mu)*rstd*gm.x + bt.x) * zz.x;
        o4.y = ((v[m][1]-mu)*rstd*gm.y + bt.y) * zz.y;
        o4.z = ((v[m][2]-mu)*rstd*gm.z + bt.z) * zz.z;
        o4.w = ((v[m][3]-mu)*rstd*gm.w + bt.w) * zz.w;
        *(float4*)(ymp + e4) = o4;
    }
}

// ------------------------- launcher -----------------------------------------
extern "C" void kernel_launch(void* const* d_in, const int* in_sizes, int n_in,
                              void* d_out, int out_size)
{
    const float* x    = (const float*)d_in[0];
    const float* ipw  = (const float*)d_in[1];
    const float* cw   = (const float*)d_in[2];
    const float* cb   = (const float*)d_in[3];
    const float* xpw  = (const float*)d_in[4];
    const float* dtw  = (const float*)d_in[5];
    const float* dtb  = (const float*)d_in[6];
    const float* alog = (const float*)d_in[7];
    const float* Ds   = (const float*)d_in[8];
    const float* lng  = (const float*)d_in[9];
    const float* lnb  = (const float*)d_in[10];
    const float* opw  = (const float*)d_in[11];
    float* out = (float*)d_out;

    k_gemm<DM, 1><<<dim3(128, 6), 256>>>(x, ipw, nullptr, 2*EE);
    k_conv<<<dim3(4, 64, BB), 256>>>(cw, cb);
    k_gemm<EE, 0><<<dim3(128, 3), 256>>>(nullptr, xpw, nullptr, C152);
    k_prep<<<BB*KK*128, 256>>>(dtw, dtb);
    k_scan1<<<16*31*3, 256>>>(alog);
    k_scanmid<<<192, 256>>>(alog);
    k_scan2<<<16*32*3, 256>>>(alog);
    k_merge<<<dim3(128, BB), 256>>>(Ds, lng, lnb);
    k_gemm<EE, 2><<<dim3(128, 2), 256>>>(nullptr, opw, out, DM);
}

// round 13
// speedup vs baseline: 1.4307x; 1.4307x over previous
#include <cuda_runtime.h>

#define BB 4
#define HHH 64
#define LL 4096
#define EE 192
#define NNS 16
#define RR 6
#define KK 4
#define DM 96
#define BL (BB*LL)
#define C152 152
#define NCH 32
#define CHL 128   // LL/NCH

typedef unsigned long long u64;

// ------------------------- device scratch (no allocations) ------------------
__device__ float g_xx[BL*EE];
__device__ float g_z [BL*EE];
__device__ float g_xc[BL*EE];
__device__ float g_P [BL*C152];
__device__ float g_delta[16*EE*LL];
__device__ float g_du   [16*EE*LL];
__device__ float g_B4[16*LL*16];
__device__ float g_C4[16*LL*16];
__device__ float g_y [16*LL*EE];       // (bk, l, e)
__device__ float g_ym[BL*EE];
// chunked-scan carries: chain = bk*EE+e in [0,3072); state slot np = lj*4+s
__device__ float g_hfin[3072*NCH*16];
__device__ float g_hin [3072*NCH*16];
__device__ float g_Sdd [3072*NCH];

__device__ __forceinline__ float ex2f(float x){
    float y; asm("ex2.approx.f32 %0, %1;" : "=f"(y) : "f"(x)); return y;
}
__device__ __forceinline__ float siluf(float x){
    return x / (1.f + __expf(-x));
}
__device__ __forceinline__ float softplusf(float x){
    return fmaxf(x, 0.f) + __logf(1.f + __expf(-fabsf(x)));
}
__device__ __forceinline__ u64 fma2(u64 a, u64 b, u64 c){
    u64 d; asm("fma.rn.f32x2 %0, %1, %2, %3;" : "=l"(d) : "l"(a), "l"(b), "l"(c));
    return d;
}
__device__ __forceinline__ u64 pack2(float x, float y){
    u64 d; asm("mov.b64 %0, {%1, %2};" : "=l"(d) : "f"(x), "f"(y));
    return d;
}
__device__ __forceinline__ void unpack2(u64 v, float& lo, float& hi){
    asm("mov.b64 {%0, %1}, %2;" : "=f"(lo), "=f"(hi) : "l"(v));
}

// ------------------------- tiled GEMM: out[m,n] = sum_k X[m,k]*W[n,k] -------
// 128x64 tile, 256 threads, 8x4 micro-tile, f32x2 packed accumulation,
// register-prefetch software pipeline over k-tiles.
template<int KD, int MODE>
__global__ void __launch_bounds__(256)
k_gemm(const float* __restrict__ Xp, const float* __restrict__ W,
       float* __restrict__ Out, int Nn)
{
    __shared__ float Xs[32][132];
    __shared__ float Ws[32][68];
    const float* __restrict__ X = (MODE==0) ? (const float*)g_xc
                                : (MODE==2) ? (const float*)g_ym : Xp;
    const int m0 = blockIdx.x * 128;
    const int n0 = blockIdx.y * 64;
    const int t  = threadIdx.x;
    const int ty = t >> 4, tx = t & 15;
    u64 acc2[4][4];
    #pragma unroll
    for (int i=0;i<4;i++)
        #pragma unroll
        for (int j=0;j<4;j++) acc2[i][j] = 0ull;

    const int lc4 = (t & 7) * 4;
    const int lr0 = t >> 3;
    const int NKC = KD/32;

    float4 xv[4], wv2[2];
    #pragma unroll
    for (int i = 0; i < 4; i++)
        xv[i] = *(const float4*)&X[(m0 + lr0 + 32*i)*KD + lc4];
    #pragma unroll
    for (int i = 0; i < 2; i++){
        int nr = n0 + lr0 + 32*i;
        wv2[i] = (nr < Nn) ? *(const float4*)&W[nr*KD + lc4]
                           : make_float4(0.f,0.f,0.f,0.f);
    }

    #pragma unroll
    for (int kc = 0; kc < NKC; kc++){
        #pragma unroll
        for (int i = 0; i < 4; i++){
            int r = lr0 + 32*i;
            Xs[lc4+0][r] = xv[i].x; Xs[lc4+1][r] = xv[i].y;
            Xs[lc4+2][r] = xv[i].z; Xs[lc4+3][r] = xv[i].w;
        }
        #pragma unroll
        for (int i = 0; i < 2; i++){
            int r = lr0 + 32*i;
            Ws[lc4+0][r] = wv2[i].x; Ws[lc4+1][r] = wv2[i].y;
            Ws[lc4+2][r] = wv2[i].z; Ws[lc4+3][r] = wv2[i].w;
        }
        __syncthreads();

        if (kc + 1 < NKC){
            #pragma unroll
            for (int i = 0; i < 4; i++)
                xv[i] = *(const float4*)&X[(m0 + lr0 + 32*i)*KD + (kc+1)*32 + lc4];
            #pragma unroll
            for (int i = 0; i < 2; i++){
                int nr = n0 + lr0 + 32*i;
                wv2[i] = (nr < Nn) ? *(const float4*)&W[nr*KD + (kc+1)*32 + lc4]
                                   : make_float4(0.f,0.f,0.f,0.f);
            }
        }

        #pragma unroll
        for (int k = 0; k < 32; k++){
            const u64* xp = (const u64*)&Xs[k][ty*8];
            u64 x2[4] = {xp[0], xp[1], xp[2], xp[3]};
            float4 wv = *(const float4*)&Ws[k][tx*4];
            u64 w2[4] = {pack2(wv.x,wv.x), pack2(wv.y,wv.y),
                         pack2(wv.z,wv.z), pack2(wv.w,wv.w)};
            #pragma unroll
            for (int i=0;i<4;i++)
                #pragma unroll
                for (int j=0;j<4;j++) acc2[i][j] = fma2(x2[i], w2[j], acc2[i][j]);
        }
        __syncthreads();
    }
    #pragma unroll
    for (int i=0;i<4;i++){
        #pragma unroll
        for (int j=0;j<4;j++){
            float lo, hi;
            unpack2(acc2[i][j], lo, hi);
            int n = n0 + tx*4 + j;
            int mA = m0 + ty*8 + 2*i;
            #pragma unroll
            for (int pp = 0; pp < 2; pp++){
                int m = mA + pp;
                float v = pp ? hi : lo;
                if (MODE == 1){
                    if (n < EE) g_xx[m*EE + n] = v;
                    else        g_z [m*EE + n - EE] = siluf(v);
                } else if (MODE == 0){
                    if (n < Nn) g_P[m*C152 + n] = v;
                } else {
                    if (n < Nn) Out[m*Nn + n] = v;
                }
            }
        }
    }
}

// ------------------------- depthwise 3x3 conv + bias + silu -----------------
__global__ void __launch_bounds__(256) k_conv(const float* __restrict__ cw, const float* __restrict__ cb)
{
    __shared__ float xs_s[3][64][48];
    __shared__ float cw_s[48][9];
    const int e0 = blockIdx.x * 48;
    const int h  = blockIdx.y;
    const int b  = blockIdx.z;
    const int t  = threadIdx.x;

    for (int idx = t; idx < 3*64*48; idx += 256){
        int row = idx / (64*48);
        int rem = idx - row*(64*48);
        int w  = rem / 48;
        int ec = rem - w*48;
        int hh = h + row - 1;
        float v = 0.f;
        if (hh >= 0 && hh < HHH)
            v = g_xx[(b*LL + hh*64 + w)*EE + e0 + ec];
        xs_s[row][w][ec] = v;
    }
    for (int idx = t; idx < 48*9; idx += 256){
        int ec = idx / 9, q = idx - ec*9;
        cw_s[ec][q] = cw[(e0+ec)*9 + q];
    }
    __syncthreads();

    for (int o = t; o < 64*48; o += 256){
        int w  = o / 48;
        int ec = o - w*48;
        float acc = cb[e0+ec];
        #pragma unroll
        for (int dh = 0; dh < 3; dh++){
            #pragma unroll
            for (int dw = 0; dw < 3; dw++){
                int ww = w + dw - 1;
                if (ww >= 0 && ww < 64)
                    acc = fmaf(xs_s[dh][ww][ec], cw_s[ec][dh*3+dw], acc);
            }
        }
        g_xc[(b*LL + h*64 + w)*EE + e0 + ec] = siluf(acc);
    }
}

// ------------------------- prep: delta/du + B4/C4 ---------------------------
// B4/C4 slot layout per l: np = lj*4 + s  <->  state n = 4*s + lj
__global__ void __launch_bounds__(256) k_prep(const float* __restrict__ dtw, const float* __restrict__ dtb)
{
    __shared__ float Pt[32][39];
    __shared__ float xr[32][193];
    __shared__ float dtws[EE*RR];
    __shared__ float dtbs[EE];
    __shared__ int   clm[32];
    const int bid = blockIdx.x;
    const int lt = bid & 127;
    const int k  = (bid >> 7) & 3;
    const int b  = bid >> 9;
    const int l0 = lt * 32;
    const int t  = threadIdx.x;

    if (t < 32){
        int l = l0 + t, cl;
        if (k == 0)      cl = l;
        else if (k == 1) cl = (l & 63)*64 + (l >> 6);
        else if (k == 2) cl = (LL-1) - l;
        else { int lp = (LL-1) - l; cl = (lp & 63)*64 + (lp >> 6); }
        clm[t] = cl;
    }
    for (int idx = t; idx < EE*RR; idx += 256) dtws[idx] = dtw[k*EE*RR + idx];
    for (int idx = t; idx < EE;    idx += 256) dtbs[idx] = dtb[k*EE + idx];
    __syncthreads();
    for (int idx = t; idx < 32*38; idx += 256){
        int r = idx / 38, c = idx - r*38;
        Pt[r][c] = g_P[(b*LL + clm[r])*C152 + k*38 + c];
    }
    for (int idx = t; idx < 32*48; idx += 256){
        int r = idx / 48, c = idx - r*48;
        float4 v = *(const float4*)&g_xc[(b*LL + clm[r])*EE + c*4];
        xr[r][c*4+0] = v.x; xr[r][c*4+1] = v.y;
        xr[r][c*4+2] = v.z; xr[r][c*4+3] = v.w;
    }
    __syncthreads();

    const int warp = t >> 5, lane = t & 31;
    const int bk = b*KK + k;
    for (int e = warp; e < EE; e += 8){
        float acc = dtbs[e];
        #pragma unroll
        for (int r = 0; r < RR; r++) acc = fmaf(Pt[lane][r], dtws[e*RR + r], acc);
        float dl = softplusf(acc);
        float u  = xr[lane][e];
        int idx = (bk*EE + e)*LL + l0 + lane;
        g_delta[idx] = dl;
        g_du[idx]    = dl * u;
    }
    for (int idx = t; idx < 32*16; idx += 256){
        int pos = idx >> 4, np = idx & 15;
        int n = 4*(np & 3) + (np >> 2);     // state index for slot np
        int o = (bk*LL + l0 + pos)*16 + np;
        g_B4[o] = Pt[pos][6  + n];
        g_C4[o] = Pt[pos][22 + n];
    }
}

// ------------------------- scan pass 1: per-chunk local (h_fin, Sdd) --------
// block = (bk, chunk, e-group-triplet): 8 warps share (bk, chunk), stage B
// into smem once; warp w covers e-group (egb*8+w). chunks 0..30 only.
// grid 16*31*3 = 1488 blocks x 256.
__global__ void __launch_bounds__(256) k_scan1(const float* __restrict__ A_logs)
{
    __shared__ float Bs[CHL*16];       // 8KB

    const int warp = threadIdx.x >> 5;
    const int lane = threadIdx.x & 31;
    int tmp = blockIdx.x;
    const int egb   = tmp % 3;  tmp /= 3;
    const int chunk = tmp % 31; tmp /= 31;
    const int bk    = tmp;
    const int eg = egb*8 + warp;                 // [0,24)
    const int e  = eg*8 + (lane >> 2);
    const int lj = lane & 3;
    const int k  = bk & 3;
    const int t  = threadIdx.x;
    const int l0 = chunk*CHL;

    // stage B tile (contiguous 8KB)
    {
        const float4* src = (const float4*)(g_B4 + ((long)bk*LL + l0)*16);
        float4* dst = (float4*)Bs;
        #pragma unroll
        for (int i = 0; i < 2; i++) dst[t + 256*i] = src[t + 256*i];
    }

    const float L2E = 1.4426950408889634f;
    float am[4]; bool okl = true;
    #pragma unroll
    for (int s = 0; s < 4; s++){
        int n = 4*s + lj;
        float av = -__expf(A_logs[(k*EE + e)*NNS + n]);
        am[s] = av * L2E;
        okl &= fabsf(av + (float)(n+1)) < 1e-4f * (float)(n+1);
    }
    const bool ok = __all_sync(0xffffffffu, okl);

    const int ch = bk*EE + e;
    const long chb = (long)ch*LL;
    const float* __restrict__ pd = g_delta + chb + l0;
    const float* __restrict__ pu = g_du    + chb + l0;

    __syncthreads();

    float h0=0.f, h1=0.f, h2=0.f, h3=0.f, sdd = 0.f;
    const float am0 = am[0];

    if (ok){
        float4 d4 = *(const float4*)(pd);
        float4 u4 = *(const float4*)(pu);
        for (int l = 0; l < CHL; l += 4){
            float4 dn, un;
            if (l + 4 < CHL){
                dn = *(const float4*)(pd + l + 4);
                un = *(const float4*)(pu + l + 4);
            }
            float dd[4] = {d4.x, d4.y, d4.z, d4.w};
            float uu[4] = {u4.x, u4.y, u4.z, u4.w};
            #pragma unroll
            for (int s = 0; s < 4; s++){
                float4 b4 = *(const float4*)(Bs + (l+s)*16 + lj*4);
                float tt = ex2f(dd[s]*am0);
                float q4 = __shfl_sync(0xffffffffu, tt, 3, 4);
                float dA1 = tt*q4, dA2 = dA1*q4, dA3 = dA2*q4;
                float us = uu[s];
                h0 = fmaf(tt,  h0, us*b4.x);
                h1 = fmaf(dA1, h1, us*b4.y);
                h2 = fmaf(dA2, h2, us*b4.z);
                h3 = fmaf(dA3, h3, us*b4.w);
            }
            sdd += dd[0] + dd[1] + dd[2] + dd[3];
            d4 = dn; u4 = un;
        }
    } else {
        #pragma unroll 1
        for (int l = 0; l < CHL; l += 4){
            float4 d4 = *(const float4*)(pd + l);
            float4 u4 = *(const float4*)(pu + l);
            float dd[4] = {d4.x, d4.y, d4.z, d4.w};
            float uu[4] = {u4.x, u4.y, u4.z, u4.w};
            #pragma unroll
            for (int s = 0; s < 4; s++){
                float4 b4 = *(const float4*)(Bs + (l+s)*16 + lj*4);
                float us = uu[s];
                h0 = fmaf(ex2f(dd[s]*am[0]), h0, us*b4.x);
                h1 = fmaf(ex2f(dd[s]*am[1]), h1, us*b4.y);
                h2 = fmaf(ex2f(dd[s]*am[2]), h2, us*b4.z);
                h3 = fmaf(ex2f(dd[s]*am[3]), h3, us*b4.w);
            }
            sdd += dd[0] + dd[1] + dd[2] + dd[3];
        }
    }
    int hb = (ch*NCH + chunk)*16 + lj*4;
    *(float4*)&g_hfin[hb] = make_float4(h0, h1, h2, h3);
    if (lj == 0) g_Sdd[ch*NCH + chunk] = sdd;
}

// ------------------------- scan mid: carry propagation ----------------------
// thread = (chain, np). grid 192 x 256.
__global__ void __launch_bounds__(256) k_scanmid(const float* __restrict__ A_logs)
{
    const int tid = blockIdx.x*256 + threadIdx.x;   // [0, 49152)
    const int ch = tid >> 4;
    const int np = tid & 15;
    const int n  = 4*(np & 3) + (np >> 2);
    const int e  = ch % EE;
    const int k  = (ch / EE) & 3;
    float a = -__expf(A_logs[(k*EE + e)*NNS + n]);

    float h = 0.f;
    #pragma unroll
    for (int c = 0; c < NCH; c++){
        g_hin[(ch*NCH + c)*16 + np] = h;
        if (c < NCH-1){
            float hf = g_hfin[(ch*NCH + c)*16 + np];
            float S = g_Sdd[ch*NCH + c];
            h = hf + __expf(a*S)*h;
        }
    }
}

// ------------------------- scan pass 2: full scan, y in (bk,l,e) ------------
// block = (bk, chunk, e-group-triplet): stage B and C into smem.
// all 32 chunks. grid 16*32*3 = 1536 blocks x 256.
__global__ void __launch_bounds__(256) k_scan2(const float* __restrict__ A_logs)
{
    __shared__ float Bs[CHL*16];       // 8KB
    __shared__ float Cs[CHL*16];       // 8KB

    const int warp = threadIdx.x >> 5;
    const int lane = threadIdx.x & 31;
    int tmp = blockIdx.x;
    const int egb   = tmp % 3;  tmp /= 3;
    const int chunk = tmp & 31;
    const int bk    = tmp >> 5;
    const int eg = egb*8 + warp;
    const int e  = eg*8 + (lane >> 2);
    const int lj = lane & 3;
    const int k  = bk & 3;
    const int t  = threadIdx.x;
    const int l0 = chunk*CHL;

    // stage B and C tiles (contiguous 8KB each)
    {
        const float4* srcB = (const float4*)(g_B4 + ((long)bk*LL + l0)*16);
        const float4* srcC = (const float4*)(g_C4 + ((long)bk*LL + l0)*16);
        float4* dstB = (float4*)Bs;
        float4* dstC = (float4*)Cs;
        #pragma unroll
        for (int i = 0; i < 2; i++){
            dstB[t + 256*i] = srcB[t + 256*i];
            dstC[t + 256*i] = srcC[t + 256*i];
        }
    }

    const float L2E = 1.4426950408889634f;
    float am[4]; bool okl = true;
    #pragma unroll
    for (int s = 0; s < 4; s++){
        int n = 4*s + lj;
        float av = -__expf(A_logs[(k*EE + e)*NNS + n]);
        am[s] = av * L2E;
        okl &= fabsf(av + (float)(n+1)) < 1e-4f * (float)(n+1);
    }
    const bool ok = __all_sync(0xffffffffu, okl);

    const int ch = bk*EE + e;
    const long chb = (long)ch*LL;
    const float* __restrict__ pd = g_delta + chb + l0;
    const float* __restrict__ pu = g_du    + chb + l0;
    float* __restrict__ py = g_y + ((long)bk*LL + l0)*EE;

    float4 h4 = *(const float4*)&g_hin[(ch*NCH + chunk)*16 + lj*4];
    float h0 = h4.x, h1 = h4.y, h2 = h4.z, h3 = h4.w;
    const float am0 = am[0];

    __syncthreads();

    if (ok){
        float4 d4 = *(const float4*)(pd);
        float4 u4 = *(const float4*)(pu);
        for (int l = 0; l < CHL; l += 4){
            float4 dn, un;
            if (l + 4 < CHL){
                dn = *(const float4*)(pd + l + 4);
                un = *(const float4*)(pu + l + 4);
            }
            float dd[4] = {d4.x, d4.y, d4.z, d4.w};
            float uu[4] = {u4.x, u4.y, u4.z, u4.w};
            float ysv = 0.f;
            #pragma unroll
            for (int s = 0; s < 4; s++){
                float4 b4 = *(const float4*)(Bs + (l+s)*16 + lj*4);
                float4 c4 = *(const float4*)(Cs + (l+s)*16 + lj*4);
                float tt = ex2f(dd[s]*am0);
                float q4 = __shfl_sync(0xffffffffu, tt, 3, 4);
                float dA1 = tt*q4, dA2 = dA1*q4, dA3 = dA2*q4;
                float us = uu[s];
                h0 = fmaf(tt,  h0, us*b4.x);
                h1 = fmaf(dA1, h1, us*b4.y);
                h2 = fmaf(dA2, h2, us*b4.z);
                h3 = fmaf(dA3, h3, us*b4.w);
                float p = h0*c4.x;
                p = fmaf(h1, c4.y, p);
                p = fmaf(h2, c4.z, p);
                p = fmaf(h3, c4.w, p);
                p += __shfl_xor_sync(0xffffffffu, p, 1);
                p += __shfl_xor_sync(0xffffffffu, p, 2);
                if (lj == s) ysv = p;
            }
            py[(long)(l + lj)*EE + e] = ysv;
            d4 = dn; u4 = un;
        }
    } else {
        #pragma unroll 1
        for (int l = 0; l < CHL; l += 4){
            float4 d4 = *(const float4*)(pd + l);
            float4 u4 = *(const float4*)(pu + l);
            float dd[4] = {d4.x, d4.y, d4.z, d4.w};
            float uu[4] = {u4.x, u4.y, u4.z, u4.w};
            float ysv = 0.f;
            #pragma unroll
            for (int s = 0; s < 4; s++){
                float4 b4 = *(const float4*)(Bs + (l+s)*16 + lj*4);
                float4 c4 = *(const float4*)(Cs + (l+s)*16 + lj*4);
                float us = uu[s];
                h0 = fmaf(ex2f(dd[s]*am[0]), h0, us*b4.x);
                h1 = fmaf(ex2f(dd[s]*am[1]), h1, us*b4.y);
                h2 = fmaf(ex2f(dd[s]*am[2]), h2, us*b4.z);
                h3 = fmaf(ex2f(dd[s]*am[3]), h3, us*b4.w);
                float p = h0*c4.x;
                p = fmaf(h1, c4.y, p);
                p = fmaf(h2, c4.z, p);
                p = fmaf(h3, c4.w, p);
                p += __shfl_xor_sync(0xffffffffu, p, 1);
                p += __shfl_xor_sync(0xffffffffu, p, 2);
                if (lj == s) ysv = p;
            }
            py[(long)(l + lj)*EE + e] = ysv;
        }
    }
}

// ------------------------- merge + D*xc + LayerNorm + gate ------------------
// block = 32 l x 8 threads; all reads are contiguous 192-float rows
__global__ void __launch_bounds__(256) k_merge(const float* __restrict__ Ds, const float* __restrict__ gamma,
                        const float* __restrict__ beta)
{
    __shared__ float sumD[EE];
    const int l0 = blockIdx.x * 32;
    const int b  = blockIdx.y;
    const int t  = threadIdx.x;
    if (t < EE) sumD[t] = Ds[t] + Ds[EE + t] + Ds[2*EE + t] + Ds[3*EE + t];
    __syncthreads();

    const int li = t >> 3, ts = t & 7;
    const int l  = l0 + li;
    const int lw = (l & 63)*64 + (l >> 6);

    const float* __restrict__ y0p = g_y + ((long)(b*4 + 0)*LL + l)*EE;
    const float* __restrict__ y1p = g_y + ((long)(b*4 + 1)*LL + lw)*EE;
    const float* __restrict__ y2p = g_y + ((long)(b*4 + 2)*LL + (LL-1-l))*EE;
    const float* __restrict__ y3p = g_y + ((long)(b*4 + 3)*LL + (LL-1-lw))*EE;
    const float* __restrict__ xcp = g_xc + (long)(b*LL + l)*EE;
    const float* __restrict__ zp  = g_z  + (long)(b*LL + l)*EE;
    float* __restrict__ ymp = g_ym + (long)(b*LL + l)*EE;

    float v[6][4];
    float s1 = 0.f, s2 = 0.f;
    #pragma unroll
    for (int m = 0; m < 6; m++){
        int e4 = (ts + 8*m)*4;
        float4 a0 = *(const float4*)(y0p + e4);
        float4 a1 = *(const float4*)(y1p + e4);
        float4 a2 = *(const float4*)(y2p + e4);
        float4 a3 = *(const float4*)(y3p + e4);
        float4 xc = *(const float4*)(xcp + e4);
        float4 sd = *(const float4*)(&sumD[e4]);
        v[m][0] = a0.x + a1.x + a2.x + a3.x + sd.x*xc.x;
        v[m][1] = a0.y + a1.y + a2.y + a3.y + sd.y*xc.y;
        v[m][2] = a0.z + a1.z + a2.z + a3.z + sd.z*xc.z;
        v[m][3] = a0.w + a1.w + a2.w + a3.w + sd.w*xc.w;
        #pragma unroll
        for (int q = 0; q < 4; q++){ s1 += v[m][q]; s2 += v[m][q]*v[m][q]; }
    }
    #pragma unroll
    for (int o = 1; o < 8; o <<= 1){
        s1 += __shfl_xor_sync(0xffffffffu, s1, o);
        s2 += __shfl_xor_sync(0xffffffffu, s2, o);
    }
    const float inv = 1.f / (float)EE;
    float mu = s1 * inv;
    float var = s2 * inv - mu*mu;
    float rstd = rsqrtf(var + 1e-5f);

    #pragma unroll
    for (int m = 0; m < 6; m++){
        int e4 = (ts + 8*m)*4;
        float4 gm = *(const float4*)(gamma + e4);
        float4 bt = *(const float4*)(beta + e4);
        float4 zz = *(const float4*)(zp + e4);
        float4 o4;
        o4.x = ((v[m][0]-mu)*rstd*gm.x + bt.x) * zz.x;
        o4.y = ((v[m][1]-mu)*rstd*gm.y + bt.y) * zz.y;
        o4.z = ((v[m][2]-mu)*rstd*gm.z + bt.z) * zz.z;
        o4.w = ((v[m][3]-mu)*rstd*gm.w + bt.w) * zz.w;
        *(float4*)(ymp + e4) = o4;
    }
}

// ------------------------- launcher -----------------------------------------
extern "C" void kernel_launch(void* const* d_in, const int* in_sizes, int n_in,
                              void* d_out, int out_size)
{
    const float* x    = (const float*)d_in[0];
    const float* ipw  = (const float*)d_in[1];
    const float* cw   = (const float*)d_in[2];
    const float* cb   = (const float*)d_in[3];
    const float* xpw  = (const float*)d_in[4];
    const float* dtw  = (const float*)d_in[5];
    const float* dtb  = (const float*)d_in[6];
    const float* alog = (const float*)d_in[7];
    const float* Ds   = (const float*)d_in[8];
    const float* lng  = (const float*)d_in[9];
    const float* lnb  = (const float*)d_in[10];
    const float* opw  = (const float*)d_in[11];
    float* out = (float*)d_out;

    k_gemm<DM, 1><<<dim3(128, 6), 256>>>(x, ipw, nullptr, 2*EE);
    k_conv<<<dim3(4, 64, BB), 256>>>(cw, cb);
    k_gemm<EE, 0><<<dim3(128, 3), 256>>>(nullptr, xpw, nullptr, C152);
    k_prep<<<BB*KK*128, 256>>>(dtw, dtb);
    k_scan1<<<16*31*3, 256>>>(alog);
    k_scanmid<<<192, 256>>>(alog);
    k_scan2<<<16*32*3, 256>>>(alog);
    k_merge<<<dim3(128, BB), 256>>>(Ds, lng, lnb);
    k_gemm<EE, 2><<<dim3(128, 2), 256>>>(nullptr, opw, out, DM);
}

// round 14
// speedup vs baseline: 1.5414x; 1.0773x over previous
#include <cuda_runtime.h>

#define BB 4
#define HHH 64
#define LL 4096
#define EE 192
#define NNS 16
#define RR 6
#define KK 4
#define DM 96
#define BL (BB*LL)
#define C152 152
#define NCH 32
#define CHL 128   // LL/NCH

typedef unsigned long long u64;

// ------------------------- device scratch (no allocations) ------------------
__device__ float g_xx[BL*EE];
__device__ float g_z [BL*EE];
__device__ float g_xc[BL*EE];
__device__ float g_P [BL*C152];
__device__ float2 g_dU2[16*LL*EE];     // {delta, delta*u} in (bk, l, e)
__device__ float g_B4[16*LL*16];       // (bk, l, n) natural state order
__device__ float g_C4[16*LL*16];
__device__ float g_y [16*LL*EE];       // (bk, l, e)
__device__ float g_ym[BL*EE];
// chunked-scan carries: chain = bk*EE+e in [0,3072); natural state order n
__device__ float g_hfin[3072*NCH*16];
__device__ float g_hin [3072*NCH*16];
__device__ float g_Sdd [3072*NCH];

__device__ __forceinline__ float ex2f(float x){
    float y; asm("ex2.approx.f32 %0, %1;" : "=f"(y) : "f"(x)); return y;
}
__device__ __forceinline__ float siluf(float x){
    return x / (1.f + __expf(-x));
}
__device__ __forceinline__ float softplusf(float x){
    return fmaxf(x, 0.f) + __logf(1.f + __expf(-fabsf(x)));
}
__device__ __forceinline__ u64 fma2(u64 a, u64 b, u64 c){
    u64 d; asm("fma.rn.f32x2 %0, %1, %2, %3;" : "=l"(d) : "l"(a), "l"(b), "l"(c));
    return d;
}
__device__ __forceinline__ u64 mul2(u64 a, u64 b){
    u64 d; asm("mul.rn.f32x2 %0, %1, %2;" : "=l"(d) : "l"(a), "l"(b));
    return d;
}
__device__ __forceinline__ u64 pack2(float x, float y){
    u64 d; asm("mov.b64 %0, {%1, %2};" : "=l"(d) : "f"(x), "f"(y));
    return d;
}
__device__ __forceinline__ void unpack2(u64 v, float& lo, float& hi){
    asm("mov.b64 {%0, %1}, %2;" : "=f"(lo), "=f"(hi) : "l"(v));
}

// ------------------------- tiled GEMM: out[m,n] = sum_k X[m,k]*W[n,k] -------
template<int KD, int MODE>
__global__ void __launch_bounds__(256)
k_gemm(const float* __restrict__ Xp, const float* __restrict__ W,
       float* __restrict__ Out, int Nn)
{
    __shared__ float Xs[32][132];
    __shared__ float Ws[32][68];
    const float* __restrict__ X = (MODE==0) ? (const float*)g_xc
                                : (MODE==2) ? (const float*)g_ym : Xp;
    const int m0 = blockIdx.x * 128;
    const int n0 = blockIdx.y * 64;
    const int t  = threadIdx.x;
    const int ty = t >> 4, tx = t & 15;
    u64 acc2[4][4];
    #pragma unroll
    for (int i=0;i<4;i++)
        #pragma unroll
        for (int j=0;j<4;j++) acc2[i][j] = 0ull;

    const int lc4 = (t & 7) * 4;
    const int lr0 = t >> 3;
    const int NKC = KD/32;

    float4 xv[4], wv2[2];
    #pragma unroll
    for (int i = 0; i < 4; i++)
        xv[i] = *(const float4*)&X[(m0 + lr0 + 32*i)*KD + lc4];
    #pragma unroll
    for (int i = 0; i < 2; i++){
        int nr = n0 + lr0 + 32*i;
        wv2[i] = (nr < Nn) ? *(const float4*)&W[nr*KD + lc4]
                           : make_float4(0.f,0.f,0.f,0.f);
    }

    #pragma unroll
    for (int kc = 0; kc < NKC; kc++){
        #pragma unroll
        for (int i = 0; i < 4; i++){
            int r = lr0 + 32*i;
            Xs[lc4+0][r] = xv[i].x; Xs[lc4+1][r] = xv[i].y;
            Xs[lc4+2][r] = xv[i].z; Xs[lc4+3][r] = xv[i].w;
        }
        #pragma unroll
        for (int i = 0; i < 2; i++){
            int r = lr0 + 32*i;
            Ws[lc4+0][r] = wv2[i].x; Ws[lc4+1][r] = wv2[i].y;
            Ws[lc4+2][r] = wv2[i].z; Ws[lc4+3][r] = wv2[i].w;
        }
        __syncthreads();

        if (kc + 1 < NKC){
            #pragma unroll
            for (int i = 0; i < 4; i++)
                xv[i] = *(const float4*)&X[(m0 + lr0 + 32*i)*KD + (kc+1)*32 + lc4];
            #pragma unroll
            for (int i = 0; i < 2; i++){
                int nr = n0 + lr0 + 32*i;
                wv2[i] = (nr < Nn) ? *(const float4*)&W[nr*KD + (kc+1)*32 + lc4]
                                   : make_float4(0.f,0.f,0.f,0.f);
            }
        }

        #pragma unroll
        for (int k = 0; k < 32; k++){
            const u64* xp = (const u64*)&Xs[k][ty*8];
            u64 x2[4] = {xp[0], xp[1], xp[2], xp[3]};
            float4 wv = *(const float4*)&Ws[k][tx*4];
            u64 w2[4] = {pack2(wv.x,wv.x), pack2(wv.y,wv.y),
                         pack2(wv.z,wv.z), pack2(wv.w,wv.w)};
            #pragma unroll
            for (int i=0;i<4;i++)
                #pragma unroll
                for (int j=0;j<4;j++) acc2[i][j] = fma2(x2[i], w2[j], acc2[i][j]);
        }
        __syncthreads();
    }
    #pragma unroll
    for (int i=0;i<4;i++){
        #pragma unroll
        for (int j=0;j<4;j++){
            float lo, hi;
            unpack2(acc2[i][j], lo, hi);
            int n = n0 + tx*4 + j;
            int mA = m0 + ty*8 + 2*i;
            #pragma unroll
            for (int pp = 0; pp < 2; pp++){
                int m = mA + pp;
                float v = pp ? hi : lo;
                if (MODE == 1){
                    if (n < EE) g_xx[m*EE + n] = v;
                    else        g_z [m*EE + n - EE] = siluf(v);
                } else if (MODE == 0){
                    if (n < Nn) g_P[m*C152 + n] = v;
                } else {
                    if (n < Nn) Out[m*Nn + n] = v;
                }
            }
        }
    }
}

// ------------------------- depthwise 3x3 conv + bias + silu -----------------
__global__ void __launch_bounds__(256) k_conv(const float* __restrict__ cw, const float* __restrict__ cb)
{
    __shared__ float xs_s[3][64][48];
    __shared__ float cw_s[48][9];
    const int e0 = blockIdx.x * 48;
    const int h  = blockIdx.y;
    const int b  = blockIdx.z;
    const int t  = threadIdx.x;

    for (int idx = t; idx < 3*64*48; idx += 256){
        int row = idx / (64*48);
        int rem = idx - row*(64*48);
        int w  = rem / 48;
        int ec = rem - w*48;
        int hh = h + row - 1;
        float v = 0.f;
        if (hh >= 0 && hh < HHH)
            v = g_xx[(b*LL + hh*64 + w)*EE + e0 + ec];
        xs_s[row][w][ec] = v;
    }
    for (int idx = t; idx < 48*9; idx += 256){
        int ec = idx / 9, q = idx - ec*9;
        cw_s[ec][q] = cw[(e0+ec)*9 + q];
    }
    __syncthreads();

    for (int o = t; o < 64*48; o += 256){
        int w  = o / 48;
        int ec = o - w*48;
        float acc = cb[e0+ec];
        #pragma unroll
        for (int dh = 0; dh < 3; dh++){
            #pragma unroll
            for (int dw = 0; dw < 3; dw++){
                int ww = w + dw - 1;
                if (ww >= 0 && ww < 64)
                    acc = fmaf(xs_s[dh][ww][ec], cw_s[ec][dh*3+dw], acc);
            }
        }
        g_xc[(b*LL + h*64 + w)*EE + e0 + ec] = siluf(acc);
    }
}

// ------------------------- prep: {delta,du} (bk,l,e) + B4/C4 natural --------
__global__ void __launch_bounds__(256) k_prep(const float* __restrict__ dtw, const float* __restrict__ dtb)
{
    __shared__ float Pt[32][39];
    __shared__ float xr[32][193];
    __shared__ float dtws[EE*RR];
    __shared__ float dtbs[EE];
    __shared__ int   clm[32];
    const int bid = blockIdx.x;
    const int lt = bid & 127;
    const int k  = (bid >> 7) & 3;
    const int b  = bid >> 9;
    const int l0 = lt * 32;
    const int t  = threadIdx.x;

    if (t < 32){
        int l = l0 + t, cl;
        if (k == 0)      cl = l;
        else if (k == 1) cl = (l & 63)*64 + (l >> 6);
        else if (k == 2) cl = (LL-1) - l;
        else { int lp = (LL-1) - l; cl = (lp & 63)*64 + (lp >> 6); }
        clm[t] = cl;
    }
    for (int idx = t; idx < EE*RR; idx += 256) dtws[idx] = dtw[k*EE*RR + idx];
    for (int idx = t; idx < EE;    idx += 256) dtbs[idx] = dtb[k*EE + idx];
    __syncthreads();
    for (int idx = t; idx < 32*38; idx += 256){
        int r = idx / 38, c = idx - r*38;
        Pt[r][c] = g_P[(b*LL + clm[r])*C152 + k*38 + c];
    }
    for (int idx = t; idx < 32*48; idx += 256){
        int r = idx / 48, c = idx - r*48;
        float4 v = *(const float4*)&g_xc[(b*LL + clm[r])*EE + c*4];
        xr[r][c*4+0] = v.x; xr[r][c*4+1] = v.y;
        xr[r][c*4+2] = v.z; xr[r][c*4+3] = v.w;
    }
    __syncthreads();

    const int bk = b*KK + k;
    if (t < EE){
        const int e = t;
        float wreg[RR];
        #pragma unroll
        for (int r = 0; r < RR; r++) wreg[r] = dtws[e*RR + r];
        const float db = dtbs[e];
        #pragma unroll 4
        for (int l = 0; l < 32; l++){
            float acc = db;
            #pragma unroll
            for (int r = 0; r < RR; r++) acc = fmaf(Pt[l][r], wreg[r], acc);
            float dl = softplusf(acc);
            float u  = xr[l][e];
            g_dU2[((long)bk*LL + l0 + l)*EE + e] = make_float2(dl, dl*u);
        }
    }
    for (int idx = t; idx < 32*16; idx += 256){
        int pos = idx >> 4, n = idx & 15;
        int o = (bk*LL + l0 + pos)*16 + n;
        g_B4[o] = Pt[pos][6  + n];
        g_C4[o] = Pt[pos][22 + n];
    }
}

// ------------------------- scan pass 1: lane = full chain (16 states) -------
// block = (bk, chunk): 6 warps x 32 lanes = 192 e-chains; B staged to smem.
// chunks 0..30. grid 16*31 = 496 blocks.
__global__ void __launch_bounds__(192) k_scan1(const float* __restrict__ A_logs)
{
    __shared__ float Bs[CHL*16];       // 8KB

    const int t    = threadIdx.x;
    const int lane = t & 31;
    const int w    = t >> 5;
    const int bk    = blockIdx.x / 31;
    const int chunk = blockIdx.x - bk*31;
    const int e  = w*32 + lane;
    const int k  = bk & 3;
    const int l0 = chunk*CHL;

    {
        const float4* src = (const float4*)(g_B4 + ((long)bk*LL + l0)*16);
        float4* dst = (float4*)Bs;
        for (int i = t; i < CHL*4; i += 192) dst[i] = src[i];
    }

    const float L2E = 1.4426950408889634f;
    const int abase = (k*EE + e)*NNS;
    bool okl = true;
    #pragma unroll
    for (int n = 0; n < 16; n++){
        float av = -__expf(A_logs[abase + n]);
        okl &= fabsf(av + (float)(n+1)) < 1e-4f*(float)(n+1);
    }
    const bool ok = __all_sync(0xffffffffu, okl);

    const int ch = bk*EE + e;
    const float2* __restrict__ pdu = g_dU2 + ((long)bk*LL + l0)*EE + e;

    __syncthreads();

    u64 h2[8];
    #pragma unroll
    for (int j = 0; j < 8; j++) h2[j] = 0ull;
    float sdd = 0.f;

    if (ok){
        #pragma unroll 4
        for (int l = 0; l < CHL; l++){
            float2 du = pdu[(long)l*EE];
            float tt = ex2f(-L2E*du.x);
            float t2 = tt*tt, t4v = t2*t2;
            u64 s2 = pack2(t2,t2), s4 = pack2(t4v,t4v);
            u64 d0 = pack2(tt, t2);
            u64 d1 = mul2(d0, s2);
            u64 d2 = mul2(d0, s4);
            u64 d3 = mul2(d1, s4);
            u64 d4 = mul2(d2, s4);
            u64 d5 = mul2(d3, s4);
            u64 d6 = mul2(d4, s4);
            u64 d7 = mul2(d5, s4);
            u64 us2 = pack2(du.y, du.y);
            const u64* bp = (const u64*)(Bs + l*16);
            h2[0] = fma2(d0, h2[0], mul2(us2, bp[0]));
            h2[1] = fma2(d1, h2[1], mul2(us2, bp[1]));
            h2[2] = fma2(d2, h2[2], mul2(us2, bp[2]));
            h2[3] = fma2(d3, h2[3], mul2(us2, bp[3]));
            h2[4] = fma2(d4, h2[4], mul2(us2, bp[4]));
            h2[5] = fma2(d5, h2[5], mul2(us2, bp[5]));
            h2[6] = fma2(d6, h2[6], mul2(us2, bp[6]));
            h2[7] = fma2(d7, h2[7], mul2(us2, bp[7]));
            sdd += du.x;
        }
    } else {
        #pragma unroll 1
        for (int l = 0; l < CHL; l++){
            float2 du = pdu[(long)l*EE];
            u64 us2 = pack2(du.y, du.y);
            const u64* bp = (const u64*)(Bs + l*16);
            #pragma unroll
            for (int j = 0; j < 8; j++){
                float alo = -L2E*__expf(A_logs[abase + 2*j]);
                float ahi = -L2E*__expf(A_logs[abase + 2*j+1]);
                u64 dA = pack2(ex2f(du.x*alo), ex2f(du.x*ahi));
                h2[j] = fma2(dA, h2[j], mul2(us2, bp[j]));
            }
            sdd += du.x;
        }
    }
    u64* hfo = (u64*)&g_hfin[((long)ch*NCH + chunk)*16];
    #pragma unroll
    for (int j = 0; j < 8; j++) hfo[j] = h2[j];
    g_Sdd[ch*NCH + chunk] = sdd;
}

// ------------------------- scan mid: carry propagation ----------------------
__global__ void __launch_bounds__(256) k_scanmid(const float* __restrict__ A_logs)
{
    const int tid = blockIdx.x*256 + threadIdx.x;   // [0, 49152)
    const int ch = tid >> 4;
    const int n  = tid & 15;
    const int e  = ch % EE;
    const int k  = (ch / EE) & 3;
    float a = -__expf(A_logs[(k*EE + e)*NNS + n]);

    float h = 0.f;
    #pragma unroll
    for (int c = 0; c < NCH; c++){
        g_hin[((long)ch*NCH + c)*16 + n] = h;
        if (c < NCH-1){
            float hf = g_hfin[((long)ch*NCH + c)*16 + n];
            float S = g_Sdd[ch*NCH + c];
            h = hf + __expf(a*S)*h;
        }
    }
}

// ------------------------- scan pass 2: lane = full chain, with y -----------
// block = (bk, chunk): 192 threads; B,C staged. all 32 chunks: grid 512.
__global__ void __launch_bounds__(192) k_scan2(const float* __restrict__ A_logs)
{
    __shared__ float Bs[CHL*16];       // 8KB
    __shared__ float Cs[CHL*16];       // 8KB

    const int t    = threadIdx.x;
    const int lane = t & 31;
    const int w    = t >> 5;
    const int bk    = blockIdx.x >> 5;
    const int chunk = blockIdx.x & 31;
    const int e  = w*32 + lane;
    const int k  = bk & 3;
    const int l0 = chunk*CHL;

    {
        const float4* srcB = (const float4*)(g_B4 + ((long)bk*LL + l0)*16);
        const float4* srcC = (const float4*)(g_C4 + ((long)bk*LL + l0)*16);
        float4* dstB = (float4*)Bs;
        float4* dstC = (float4*)Cs;
        for (int i = t; i < CHL*4; i += 192){
            dstB[i] = srcB[i];
            dstC[i] = srcC[i];
        }
    }

    const float L2E = 1.4426950408889634f;
    const int abase = (k*EE + e)*NNS;
    bool okl = true;
    #pragma unroll
    for (int n = 0; n < 16; n++){
        float av = -__expf(A_logs[abase + n]);
        okl &= fabsf(av + (float)(n+1)) < 1e-4f*(float)(n+1);
    }
    const bool ok = __all_sync(0xffffffffu, okl);

    const int ch = bk*EE + e;
    const float2* __restrict__ pdu = g_dU2 + ((long)bk*LL + l0)*EE + e;
    float* __restrict__ py = g_y + ((long)bk*LL + l0)*EE + e;

    u64 h2[8];
    {
        const u64* hp = (const u64*)&g_hin[((long)ch*NCH + chunk)*16];
        #pragma unroll
        for (int j = 0; j < 8; j++) h2[j] = hp[j];
    }

    __syncthreads();

    if (ok){
        #pragma unroll 4
        for (int l = 0; l < CHL; l++){
            float2 du = pdu[(long)l*EE];
            float tt = ex2f(-L2E*du.x);
            float t2 = tt*tt, t4v = t2*t2;
            u64 s2 = pack2(t2,t2), s4 = pack2(t4v,t4v);
            u64 d0 = pack2(tt, t2);
            u64 d1 = mul2(d0, s2);
            u64 d2 = mul2(d0, s4);
            u64 d3 = mul2(d1, s4);
            u64 d4 = mul2(d2, s4);
            u64 d5 = mul2(d3, s4);
            u64 d6 = mul2(d4, s4);
            u64 d7 = mul2(d5, s4);
            u64 us2 = pack2(du.y, du.y);
            const u64* bp = (const u64*)(Bs + l*16);
            const u64* cp = (const u64*)(Cs + l*16);
            h2[0] = fma2(d0, h2[0], mul2(us2, bp[0]));
            h2[1] = fma2(d1, h2[1], mul2(us2, bp[1]));
            h2[2] = fma2(d2, h2[2], mul2(us2, bp[2]));
            h2[3] = fma2(d3, h2[3], mul2(us2, bp[3]));
            h2[4] = fma2(d4, h2[4], mul2(us2, bp[4]));
            h2[5] = fma2(d5, h2[5], mul2(us2, bp[5]));
            h2[6] = fma2(d6, h2[6], mul2(us2, bp[6]));
            h2[7] = fma2(d7, h2[7], mul2(us2, bp[7]));
            u64 acc = mul2(h2[0], cp[0]);
            acc = fma2(h2[1], cp[1], acc);
            acc = fma2(h2[2], cp[2], acc);
            acc = fma2(h2[3], cp[3], acc);
            acc = fma2(h2[4], cp[4], acc);
            acc = fma2(h2[5], cp[5], acc);
            acc = fma2(h2[6], cp[6], acc);
            acc = fma2(h2[7], cp[7], acc);
            float lo, hi; unpack2(acc, lo, hi);
            py[(long)l*EE] = lo + hi;
        }
    } else {
        #pragma unroll 1
        for (int l = 0; l < CHL; l++){
            float2 du = pdu[(long)l*EE];
            u64 us2 = pack2(du.y, du.y);
            const u64* bp = (const u64*)(Bs + l*16);
            const u64* cp = (const u64*)(Cs + l*16);
            u64 acc = 0ull;
            #pragma unroll
            for (int j = 0; j < 8; j++){
                float alo = -L2E*__expf(A_logs[abase + 2*j]);
                float ahi = -L2E*__expf(A_logs[abase + 2*j+1]);
                u64 dA = pack2(ex2f(du.x*alo), ex2f(du.x*ahi));
                h2[j] = fma2(dA, h2[j], mul2(us2, bp[j]));
                acc = fma2(h2[j], cp[j], acc);
            }
            float lo, hi; unpack2(acc, lo, hi);
            py[(long)l*EE] = lo + hi;
        }
    }
}

// ------------------------- merge + D*xc + LayerNorm + gate ------------------
__global__ void __launch_bounds__(256) k_merge(const float* __restrict__ Ds, const float* __restrict__ gamma,
                        const float* __restrict__ beta)
{
    __shared__ float sumD[EE];
    const int l0 = blockIdx.x * 32;
    const int b  = blockIdx.y;
    const int t  = threadIdx.x;
    if (t < EE) sumD[t] = Ds[t] + Ds[EE + t] + Ds[2*EE + t] + Ds[3*EE + t];
    __syncthreads();

    const int li = t >> 3, ts = t & 7;
    const int l  = l0 + li;
    const int lw = (l & 63)*64 + (l >> 6);

    const float* __restrict__ y0p = g_y + ((long)(b*4 + 0)*LL + l)*EE;
    const float* __restrict__ y1p = g_y + ((long)(b*4 + 1)*LL + lw)*EE;
    const float* __restrict__ y2p = g_y + ((long)(b*4 + 2)*LL + (LL-1-l))*EE;
    const float* __restrict__ y3p = g_y + ((long)(b*4 + 3)*LL + (LL-1-lw))*EE;
    const float* __restrict__ xcp = g_xc + (long)(b*LL + l)*EE;
    const float* __restrict__ zp  = g_z  + (long)(b*LL + l)*EE;
    float* __restrict__ ymp = g_ym + (long)(b*LL + l)*EE;

    float v[6][4];
    float s1 = 0.f, s2 = 0.f;
    #pragma unroll
    for (int m = 0; m < 6; m++){
        int e4 = (ts + 8*m)*4;
        float4 a0 = *(const float4*)(y0p + e4);
        float4 a1 = *(const float4*)(y1p + e4);
        float4 a2 = *(const float4*)(y2p + e4);
        float4 a3 = *(const float4*)(y3p + e4);
        float4 xc = *(const float4*)(xcp + e4);
        float4 sd = *(const float4*)(&sumD[e4]);
        v[m][0] = a0.x + a1.x + a2.x + a3.x + sd.x*xc.x;
        v[m][1] = a0.y + a1.y + a2.y + a3.y + sd.y*xc.y;
        v[m][2] = a0.z + a1.z + a2.z + a3.z + sd.z*xc.z;
        v[m][3] = a0.w + a1.w + a2.w + a3.w + sd.w*xc.w;
        #pragma unroll
        for (int q = 0; q < 4; q++){ s1 += v[m][q]; s2 += v[m][q]*v[m][q]; }
    }
    #pragma unroll
    for (int o = 1; o < 8; o <<= 1){
        s1 += __shfl_xor_sync(0xffffffffu, s1, o);
        s2 += __shfl_xor_sync(0xffffffffu, s2, o);
    }
    const float inv = 1.f / (float)EE;
    float mu = s1 * inv;
    float var = s2 * inv - mu*mu;
    float rstd = rsqrtf(var + 1e-5f);

    #pragma unroll
    for (int m = 0; m < 6; m++){
        int e4 = (ts + 8*m)*4;
        float4 gm = *(const float4*)(gamma + e4);
        float4 bt = *(const float4*)(beta + e4);
        float4 zz = *(const float4*)(zp + e4);
        float4 o4;
        o4.x = ((v[m][0]-mu)*rstd*gm.x + bt.x) * zz.x;
        o4.y = ((v[m][1]-mu)*rstd*gm.y + bt.y) * zz.y;
        o4.z = ((v[m][2]-mu)*rstd*gm.z + bt.z) * zz.z;
        o4.w = ((v[m][3]-mu)*rstd*gm.w + bt.w) * zz.w;
        *(float4*)(ymp + e4) = o4;
    }
}

// ------------------------- launcher -----------------------------------------
extern "C" void kernel_launch(void* const* d_in, const int* in_sizes, int n_in,
                              void* d_out, int out_size)
{
    const float* x    = (const float*)d_in[0];
    const float* ipw  = (const float*)d_in[1];
    const float* cw   = (const float*)d_in[2];
    const float* cb   = (const float*)d_in[3];
    const float* xpw  = (const float*)d_in[4];
    const float* dtw  = (const float*)d_in[5];
    const float* dtb  = (const float*)d_in[6];
    const float* alog = (const float*)d_in[7];
    const float* Ds   = (const float*)d_in[8];
    const float* lng  = (const float*)d_in[9];
    const float* lnb  = (const float*)d_in[10];
    const float* opw  = (const float*)d_in[11];
    float* out = (float*)d_out;

    k_gemm<DM, 1><<<dim3(128, 6), 256>>>(x, ipw, nullptr, 2*EE);
    k_conv<<<dim3(4, 64, BB), 256>>>(cw, cb);
    k_gemm<EE, 0><<<dim3(128, 3), 256>>>(nullptr, xpw, nullptr, C152);
    k_prep<<<BB*KK*128, 256>>>(dtw, dtb);
    k_scan1<<<16*31, 192>>>(alog);
    k_scanmid<<<192, 256>>>(alog);
    k_scan2<<<16*32, 192>>>(alog);
    k_merge<<<dim3(128, BB), 256>>>(Ds, lng, lnb);
    k_gemm<EE, 2><<<dim3(128, 2), 256>>>(nullptr, opw, out, DM);
}